// round 4
// baseline (speedup 1.0000x reference)
#include <cuda_runtime.h>
#include <math.h>

#define NN 4096
#define EE 131072
#define HIDD 64
#define OUTD 86
#define OUTP 88
#define BB 16
#define NHEADS 4
#define DH 16
#define CHUNKS 16
#define CKEYS (NN / CHUNKS)   // 256 keys per chunk

typedef unsigned long long ull;

// ------------------------- f32x2 packed helpers ----------------------------
__device__ __forceinline__ ull pk2(float lo, float hi) {
    ull r; asm("mov.b64 %0,{%1,%2};" : "=l"(r) : "f"(lo), "f"(hi)); return r;
}
__device__ __forceinline__ void upk2(ull v, float& lo, float& hi) {
    asm("mov.b64 {%0,%1},%2;" : "=f"(lo), "=f"(hi) : "l"(v));
}
__device__ __forceinline__ ull fma2(ull a, ull b, ull c) {
    ull d; asm("fma.rn.f32x2 %0,%1,%2,%3;" : "=l"(d) : "l"(a), "l"(b), "l"(c)); return d;
}
__device__ __forceinline__ ull mul2(ull a, ull b) {
    ull d; asm("mul.rn.f32x2 %0,%1,%2;" : "=l"(d) : "l"(a), "l"(b)); return d;
}
__device__ __forceinline__ float ex2(float x) {
    float y; asm("ex2.approx.ftz.f32 %0,%1;" : "=f"(y) : "f"(x)); return y;
}

// ------------------------- scratch -----------------------------------------
__device__ float g_deg[NN];
__device__ float g_dis[NN];
__device__ float g_hw[NN * HIDD];
__device__ float g_h[NN * HIDD];
__device__ float g_qkv[NN * 3 * HIDD];
__device__ float g_o[NN * HIDD];
__device__ float g_h2w[NN * OUTP];
__device__ float g_pool[BB * OUTD];
__device__ float g_cnt[BB];
__device__ int   g_hist[NN];
__device__ int   g_off[NN + 1];
__device__ int   g_cur[NN];
__device__ int   g_esrc[EE];
__device__ float g_ew[EE];
__device__ float g_pl[NHEADS * CHUNKS * NN];
__device__ float g_pacc[NHEADS * CHUNKS * NN * DH];
__device__ float g_Wc[OUTD * 64];
__device__ float g_bc[OUTD];

// ------------------------- init --------------------------------------------
__global__ void init_kernel() {
    int idx = blockIdx.x * blockDim.x + threadIdx.x;
    if (idx < NN) { g_hist[idx] = 0; g_deg[idx] = 1.0f; }
    if (idx < BB * OUTD) g_pool[idx] = 0.0f;
    if (idx < BB) g_cnt[idx] = 0.0f;
}

__global__ void accum_kernel(const int* __restrict__ ei, const float* __restrict__ ea,
                             const int* __restrict__ batch) {
    int e = blockIdx.x * blockDim.x + threadIdx.x;
    if (e < EE) {
        int d = ei[EE + e];
        atomicAdd(&g_deg[d], ea[e]);
        atomicAdd(&g_hist[d], 1);
    }
    if (e < NN) atomicAdd(&g_cnt[batch[e]], 1.0f);
}

__global__ void dis_kernel() {
    int i = blockIdx.x * blockDim.x + threadIdx.x;
    if (i < NN) g_dis[i] = rsqrtf(g_deg[i]);
}

// 1 block, 1024 threads: exclusive scan of g_hist (4096 bins)
__global__ void scan_kernel() {
    __shared__ int sh[1024];
    int t = threadIdx.x;
    int c0 = g_hist[t * 4], c1 = g_hist[t * 4 + 1];
    int c2 = g_hist[t * 4 + 2], c3 = g_hist[t * 4 + 3];
    int s = c0 + c1 + c2 + c3;
    sh[t] = s;
    __syncthreads();
    int val = s;
    for (int off = 1; off < 1024; off <<= 1) {
        int v = (t >= off) ? sh[t - off] : 0;
        __syncthreads();
        val += v;
        sh[t] = val;
        __syncthreads();
    }
    int excl = val - s;
    int o0 = excl, o1 = excl + c0, o2 = o1 + c1, o3 = o2 + c2;
    g_off[t * 4] = o0;     g_cur[t * 4] = o0;
    g_off[t * 4 + 1] = o1; g_cur[t * 4 + 1] = o1;
    g_off[t * 4 + 2] = o2; g_cur[t * 4 + 2] = o2;
    g_off[t * 4 + 3] = o3; g_cur[t * 4 + 3] = o3;
    if (t == 0) g_off[NN] = EE;
}

__global__ void fill_kernel(const int* __restrict__ ei, const float* __restrict__ ea) {
    int e = blockIdx.x * blockDim.x + threadIdx.x;
    if (e >= EE) return;
    int s = ei[e];
    int d = ei[EE + e];
    float w = g_dis[s] * ea[e] * g_dis[d];
    int pos = atomicAdd(&g_cur[d], 1);
    g_esrc[pos] = s;
    g_ew[pos] = w;
}

// ------------------------- GEMM (warp-per-2-rows, W prefetch) --------------
template <int KOUT, int OST, bool BIAS>
__global__ void __launch_bounds__(256) rowgemm(const float* __restrict__ in,
                                               const float* __restrict__ W,
                                               const float* __restrict__ bias,
                                               float* __restrict__ out) {
    constexpr int CT = (KOUT + 31) / 32;
    __shared__ __align__(16) float xsh[16][64];
    int lane = threadIdx.x & 31;
    int warp = threadIdx.x >> 5;
    int row0 = blockIdx.x * 16;
    {
        int r = threadIdx.x >> 4, c4 = threadIdx.x & 15;
        *(float4*)&xsh[r][c4 * 4] = *(const float4*)&in[(row0 + r) * 64 + c4 * 4];
    }
    __syncthreads();

    int r0 = warp * 2;
    float4 wb[CT];
#pragma unroll
    for (int j = 0; j < CT; j++) {
        int c = lane + j * 32;
        wb[j] = ((KOUT & 31) == 0 || c < KOUT) ? *(const float4*)&W[c * 64]
                                               : make_float4(0.f, 0.f, 0.f, 0.f);
    }
    float acc[2][CT];
#pragma unroll
    for (int i = 0; i < 2; i++)
#pragma unroll
        for (int j = 0; j < CT; j++) acc[i][j] = 0.0f;

#pragma unroll
    for (int k4 = 0; k4 < 16; k4++) {
        float4 wc[CT];
#pragma unroll
        for (int j = 0; j < CT; j++) wc[j] = wb[j];
        if (k4 < 15) {
#pragma unroll
            for (int j = 0; j < CT; j++) {
                int c = lane + j * 32;
                wb[j] = ((KOUT & 31) == 0 || c < KOUT)
                            ? *(const float4*)&W[c * 64 + (k4 + 1) * 4]
                            : make_float4(0.f, 0.f, 0.f, 0.f);
            }
        }
        float4 xa = *(const float4*)&xsh[r0][k4 * 4];
        float4 xb = *(const float4*)&xsh[r0 + 1][k4 * 4];
#pragma unroll
        for (int j = 0; j < CT; j++) {
            acc[0][j] = fmaf(xa.x, wc[j].x, acc[0][j]); acc[0][j] = fmaf(xa.y, wc[j].y, acc[0][j]);
            acc[0][j] = fmaf(xa.z, wc[j].z, acc[0][j]); acc[0][j] = fmaf(xa.w, wc[j].w, acc[0][j]);
            acc[1][j] = fmaf(xb.x, wc[j].x, acc[1][j]); acc[1][j] = fmaf(xb.y, wc[j].y, acc[1][j]);
            acc[1][j] = fmaf(xb.z, wc[j].z, acc[1][j]); acc[1][j] = fmaf(xb.w, wc[j].w, acc[1][j]);
        }
    }
#pragma unroll
    for (int i = 0; i < 2; i++) {
        int r = row0 + r0 + i;
#pragma unroll
        for (int j = 0; j < CT; j++) {
            int c = lane + j * 32;
            if ((KOUT & 31) == 0 || c < KOUT) {
                float v = acc[i][j];
                if (BIAS) v += bias[c];
                out[r * OST + c] = v;
            }
        }
    }
}

// ------------------------- GCN1 gather (warp per node) ---------------------
__global__ void gather1_kernel(const float* __restrict__ b1) {
    int gt = blockIdx.x * blockDim.x + threadIdx.x;
    int n = gt >> 5, lane = gt & 31;
    if (n >= NN) return;
    int i = g_off[n], e1 = g_off[n + 1];
    float a0 = 0.f, a1 = 0.f;
    for (; i + 1 < e1; i += 2) {
        int sA = g_esrc[i], sB = g_esrc[i + 1];
        float wA = g_ew[i], wB = g_ew[i + 1];
        a0 = fmaf(wA, g_hw[sA * 64 + lane], a0);
        a1 = fmaf(wA, g_hw[sA * 64 + 32 + lane], a1);
        a0 = fmaf(wB, g_hw[sB * 64 + lane], a0);
        a1 = fmaf(wB, g_hw[sB * 64 + 32 + lane], a1);
    }
    if (i < e1) {
        int s = g_esrc[i]; float w = g_ew[i];
        a0 = fmaf(w, g_hw[s * 64 + lane], a0);
        a1 = fmaf(w, g_hw[s * 64 + 32 + lane], a1);
    }
    float di = g_dis[n], d2 = di * di;
    float v0 = a0 + d2 * g_hw[n * 64 + lane] + b1[lane];
    float v1 = a1 + d2 * g_hw[n * 64 + 32 + lane] + b1[lane + 32];
    g_h[n * 64 + lane] = fmaxf(v0, 0.f);
    g_h[n * 64 + 32 + lane] = fmaxf(v1, 0.f);
}

// ------------------------- attention: fixed-base softmax, split-K ----------
// grid (NN/256, NHEADS, CHUNKS), block 128. Warp: 64 queries (lane, lane+32),
// iterates its chunk's 256 keys via smem (64-key tiles).
__global__ void __launch_bounds__(128, 4) attn_kernel() {
    int h = blockIdx.y, chunk = blockIdx.z;
    int lane = threadIdx.x & 31;
    int warp = threadIdx.x >> 5;
    int q0 = blockIdx.x * 256 + warp * 64 + lane;

    __shared__ __align__(16) float Ksh[64 * 16];
    __shared__ __align__(16) float Vsh[64 * 16];

    const float SC = 0.25f * 1.44269504088896f;  // (1/sqrt(dh)) * log2(e)
    ull q2[2][8];
#pragma unroll
    for (int qq = 0; qq < 2; qq++) {
        const float* qp = g_qkv + (q0 + qq * 32) * 192 + h * DH;
#pragma unroll
        for (int dp = 0; dp < 8; dp++)
            q2[qq][dp] = pk2(qp[2 * dp] * SC, qp[2 * dp + 1] * SC);
    }
    float l0 = 0.f, l1 = 0.f;
    ull acc[2][8];
#pragma unroll
    for (int qq = 0; qq < 2; qq++)
#pragma unroll
        for (int dp = 0; dp < 8; dp++) acc[qq][dp] = 0ull;

    for (int t = 0; t < CKEYS / 64; t++) {
        int key0 = chunk * CKEYS + t * 64;
        __syncthreads();
#pragma unroll
        for (int i = threadIdx.x; i < 256; i += 128) {
            int j = i >> 2, c4 = i & 3;
            const float* kb = g_qkv + (key0 + j) * 192 + 64 + h * DH + c4 * 4;
            *(float4*)&Ksh[j * 16 + c4 * 4] = *(const float4*)kb;
            *(float4*)&Vsh[j * 16 + c4 * 4] = *(const float4*)(kb + 64);
        }
        __syncthreads();

#pragma unroll 4
        for (int j = 0; j < 64; j++) {
            const ulonglong2* kr = (const ulonglong2*)&Ksh[j * 16];
            ulonglong2 ka = kr[0], kb = kr[1], kc = kr[2], kd = kr[3];
            float p0, p1;
            {
                ull s2 = mul2(q2[0][0], ka.x); s2 = fma2(q2[0][1], ka.y, s2);
                s2 = fma2(q2[0][2], kb.x, s2); s2 = fma2(q2[0][3], kb.y, s2);
                s2 = fma2(q2[0][4], kc.x, s2); s2 = fma2(q2[0][5], kc.y, s2);
                s2 = fma2(q2[0][6], kd.x, s2); s2 = fma2(q2[0][7], kd.y, s2);
                float lo, hi; upk2(s2, lo, hi);
                p0 = ex2(lo + hi);
            }
            {
                ull s2 = mul2(q2[1][0], ka.x); s2 = fma2(q2[1][1], ka.y, s2);
                s2 = fma2(q2[1][2], kb.x, s2); s2 = fma2(q2[1][3], kb.y, s2);
                s2 = fma2(q2[1][4], kc.x, s2); s2 = fma2(q2[1][5], kc.y, s2);
                s2 = fma2(q2[1][6], kd.x, s2); s2 = fma2(q2[1][7], kd.y, s2);
                float lo, hi; upk2(s2, lo, hi);
                p1 = ex2(lo + hi);
            }
            l0 += p0; l1 += p1;
            ull pp0 = pk2(p0, p0), pp1 = pk2(p1, p1);
            const ulonglong2* vr = (const ulonglong2*)&Vsh[j * 16];
            ulonglong2 va = vr[0], vb = vr[1], vc = vr[2], vd = vr[3];
            acc[0][0] = fma2(pp0, va.x, acc[0][0]); acc[0][1] = fma2(pp0, va.y, acc[0][1]);
            acc[0][2] = fma2(pp0, vb.x, acc[0][2]); acc[0][3] = fma2(pp0, vb.y, acc[0][3]);
            acc[0][4] = fma2(pp0, vc.x, acc[0][4]); acc[0][5] = fma2(pp0, vc.y, acc[0][5]);
            acc[0][6] = fma2(pp0, vd.x, acc[0][6]); acc[0][7] = fma2(pp0, vd.y, acc[0][7]);
            acc[1][0] = fma2(pp1, va.x, acc[1][0]); acc[1][1] = fma2(pp1, va.y, acc[1][1]);
            acc[1][2] = fma2(pp1, vb.x, acc[1][2]); acc[1][3] = fma2(pp1, vb.y, acc[1][3]);
            acc[1][4] = fma2(pp1, vc.x, acc[1][4]); acc[1][5] = fma2(pp1, vc.y, acc[1][5]);
            acc[1][6] = fma2(pp1, vd.x, acc[1][6]); acc[1][7] = fma2(pp1, vd.y, acc[1][7]);
        }
    }

#pragma unroll
    for (int qq = 0; qq < 2; qq++) {
        int q = q0 + qq * 32;
        size_t idx = ((size_t)(h * CHUNKS + chunk)) * NN + q;
        g_pl[idx] = (qq == 0) ? l0 : l1;
        ulonglong2* row = (ulonglong2*)&g_pacc[idx * DH];
#pragma unroll
        for (int d4 = 0; d4 < 4; d4++) {
            ulonglong2 w2;
            w2.x = acc[qq][d4 * 2]; w2.y = acc[qq][d4 * 2 + 1];
            row[d4] = w2;
        }
    }
}

__global__ void attn_combine() {
    int t = blockIdx.x * blockDim.x + threadIdx.x;
    if (t >= NHEADS * NN) return;
    int h = t >> 12, q = t & (NN - 1);
    float l = 0.f;
    float o[16];
#pragma unroll
    for (int d = 0; d < 16; d++) o[d] = 0.f;
#pragma unroll
    for (int c = 0; c < CHUNKS; c++) {
        size_t idx = ((size_t)(h * CHUNKS + c)) * NN + q;
        l += g_pl[idx];
        const float4* row = (const float4*)&g_pacc[idx * DH];
#pragma unroll
        for (int d4 = 0; d4 < 4; d4++) {
            float4 a = row[d4];
            o[d4 * 4 + 0] += a.x; o[d4 * 4 + 1] += a.y;
            o[d4 * 4 + 2] += a.z; o[d4 * 4 + 3] += a.w;
        }
    }
    float inv = 1.0f / l;
    float* op = g_o + q * 64 + h * DH;
#pragma unroll
    for (int d = 0; d < 16; d++) op[d] = o[d] * inv;
}

// ------------------------- fold Wout into W2: Wc = W2 @ Wout ----------------
__global__ void wcombine_kernel(const float* __restrict__ W2, const float* __restrict__ Wout,
                                const float* __restrict__ b_out) {
    int idx = blockIdx.x * blockDim.x + threadIdx.x;
    if (idx >= OUTD * 64) return;
    int r = idx >> 6, k = idx & 63;
    float s = 0.f;
#pragma unroll 8
    for (int c = 0; c < 64; c++) s = fmaf(W2[r * 64 + c], Wout[c * 64 + k], s);
    g_Wc[r * 64 + k] = s;
    if (k == 0) {
        float sb = 0.f;
#pragma unroll 8
        for (int c = 0; c < 64; c++) sb = fmaf(W2[r * 64 + c], b_out[c], sb);
        g_bc[r] = sb;
    }
}

// ------------------------- GCN2 gather + pool (warp per node) ---------------
__global__ void gather2_kernel(const int* __restrict__ batch, const float* __restrict__ b2) {
    int gt = blockIdx.x * blockDim.x + threadIdx.x;
    int n = gt >> 5, lane = gt & 31;
    if (n >= NN) return;
    int i = g_off[n], e1 = g_off[n + 1];
    float a0 = 0.f, a1 = 0.f, a2 = 0.f;
    bool has3 = lane < 22;
    for (; i < e1; i++) {
        int s = g_esrc[i]; float w = g_ew[i];
        const float* row = g_h2w + s * OUTP;
        a0 = fmaf(w, row[lane], a0);
        a1 = fmaf(w, row[lane + 32], a1);
        if (has3) a2 = fmaf(w, row[lane + 64], a2);
    }
    float di = g_dis[n], d2 = di * di;
    const float* self = g_h2w + n * OUTP;
    int b = batch[n];
    float v0 = a0 + d2 * self[lane] + b2[lane];
    float v1 = a1 + d2 * self[lane + 32] + b2[lane + 32];
    atomicAdd(&g_pool[b * OUTD + lane], v0);
    atomicAdd(&g_pool[b * OUTD + lane + 32], v1);
    if (has3) {
        float v2 = a2 + d2 * self[lane + 64] + b2[lane + 64];
        atomicAdd(&g_pool[b * OUTD + lane + 64], v2);
    }
}

__global__ void out_kernel(float* __restrict__ out) {
    int idx = blockIdx.x * blockDim.x + threadIdx.x;
    if (idx >= BB * OUTD) return;
    int b = idx / OUTD;
    out[idx] = g_pool[idx] / fmaxf(g_cnt[b], 1.0f);
}

// ------------------------- launch ------------------------------------------
extern "C" void kernel_launch(void* const* d_in, const int* in_sizes, int n_in,
                              void* d_out, int out_size) {
    const float* x     = (const float*)d_in[0];
    const int*   ei    = (const int*)  d_in[1];
    const float* ea    = (const float*)d_in[2];
    const int*   batch = (const int*)  d_in[3];
    const float* W1    = (const float*)d_in[4];
    const float* b1    = (const float*)d_in[5];
    const float* Win   = (const float*)d_in[6];
    const float* b_in  = (const float*)d_in[7];
    const float* Wout  = (const float*)d_in[8];
    const float* b_out = (const float*)d_in[9];
    const float* W2    = (const float*)d_in[10];
    const float* b2    = (const float*)d_in[11];
    float* out = (float*)d_out;

    float *p_hw, *p_h, *p_qkv, *p_o, *p_h2w, *p_Wc, *p_bc;
    cudaGetSymbolAddress((void**)&p_hw,  g_hw);
    cudaGetSymbolAddress((void**)&p_h,   g_h);
    cudaGetSymbolAddress((void**)&p_qkv, g_qkv);
    cudaGetSymbolAddress((void**)&p_o,   g_o);
    cudaGetSymbolAddress((void**)&p_h2w, g_h2w);
    cudaGetSymbolAddress((void**)&p_Wc,  g_Wc);
    cudaGetSymbolAddress((void**)&p_bc,  g_bc);

    // 1. init + combined weight (independent)
    init_kernel<<<NN / 256, 256>>>();
    wcombine_kernel<<<(OUTD * 64 + 255) / 256, 256>>>(W2, Wout, b_out);
    // 2. degree / histogram / batch counts, then norm + CSR
    accum_kernel<<<EE / 256, 256>>>(ei, ea, batch);
    dis_kernel<<<NN / 256, 256>>>();
    scan_kernel<<<1, 1024>>>();
    fill_kernel<<<EE / 256, 256>>>(ei, ea);
    // 3. GCN1 linear + gather
    rowgemm<64, 64, false><<<NN / 16, 256>>>(x, W1, nullptr, p_hw);
    gather1_kernel<<<NN * 32 / 256, 256>>>(b1);
    // 4. QKV projection
    rowgemm<192, 192, true><<<NN / 16, 256>>>(p_h, Win, b_in, p_qkv);
    // 5. attention (split-K partials + combine)
    attn_kernel<<<dim3(NN / 256, NHEADS, CHUNKS), 128>>>();
    attn_combine<<<(NHEADS * NN) / 256, 256>>>();
    // 6. fused (Wout∘W2) linear
    rowgemm<86, 88, true><<<NN / 16, 256>>>(p_o, p_Wc, p_bc, p_h2w);
    // 7. GCN2 gather + pool
    gather2_kernel<<<NN * 32 / 256, 256>>>(batch, b2);
    out_kernel<<<(BB * OUTD + 255) / 256, 256>>>(out);
}

// round 6
// speedup vs baseline: 1.5131x; 1.5131x over previous
#include <cuda_runtime.h>
#include <math.h>

#define NN 4096
#define EE 131072
#define HIDD 64
#define OUTD 86
#define OUTP 88
#define BB 16
#define NHEADS 4
#define DH 16
#define CHUNKS 8
#define CKEYS (NN / CHUNKS)   // 512 keys per chunk

typedef unsigned long long ull;

// ------------------------- f32x2 packed helpers ----------------------------
__device__ __forceinline__ ull pk2(float lo, float hi) {
    ull r; asm("mov.b64 %0,{%1,%2};" : "=l"(r) : "f"(lo), "f"(hi)); return r;
}
__device__ __forceinline__ void upk2(ull v, float& lo, float& hi) {
    asm("mov.b64 {%0,%1},%2;" : "=f"(lo), "=f"(hi) : "l"(v));
}
__device__ __forceinline__ ull fma2(ull a, ull b, ull c) {
    ull d; asm("fma.rn.f32x2 %0,%1,%2,%3;" : "=l"(d) : "l"(a), "l"(b), "l"(c)); return d;
}
__device__ __forceinline__ ull mul2(ull a, ull b) {
    ull d; asm("mul.rn.f32x2 %0,%1,%2;" : "=l"(d) : "l"(a), "l"(b)); return d;
}
__device__ __forceinline__ float ex2(float x) {
    float y; asm("ex2.approx.ftz.f32 %0,%1;" : "=f"(y) : "f"(x)); return y;
}

// ------------------------- scratch -----------------------------------------
__device__ float g_deg[NN];
__device__ float g_dis[NN];
__device__ float g_hw[NN * HIDD];
__device__ float g_agg1[NN * HIDD];
__device__ float g_h[NN * HIDD];
__device__ float g_qkv[NN * 3 * HIDD];
__device__ float g_o[NN * HIDD];
__device__ float g_h2w[NN * OUTP];
__device__ float g_agg2[NN * OUTP];
__device__ float g_pool[BB * OUTD];
__device__ float g_cnt[BB];
__device__ float g_pl[NHEADS * CHUNKS * NN];
__device__ float g_pacc[NHEADS * CHUNKS * NN * DH];
__device__ float g_Wc[OUTD * 64];
__device__ float g_bc[OUTD];

// ------------------------- init / degree / norm ----------------------------
__global__ void init_kernel() {
    int idx = blockIdx.x * blockDim.x + threadIdx.x;
    if (idx < NN * HIDD) g_agg1[idx] = 0.0f;
    if (idx < NN * OUTP) g_agg2[idx] = 0.0f;
    if (idx < BB * OUTD) g_pool[idx] = 0.0f;
    if (idx < BB) g_cnt[idx] = 0.0f;
    if (idx < NN) g_deg[idx] = 1.0f;   // self-loop weight 1
}

__global__ void accum_kernel(const int* __restrict__ ei, const float* __restrict__ ea,
                             const int* __restrict__ batch) {
    int e = blockIdx.x * blockDim.x + threadIdx.x;
    if (e < EE) atomicAdd(&g_deg[ei[EE + e]], ea[e]);
    if (e < NN) atomicAdd(&g_cnt[batch[e]], 1.0f);
}

__global__ void dis_kernel() {
    int i = blockIdx.x * blockDim.x + threadIdx.x;
    if (i < NN) g_dis[i] = rsqrtf(g_deg[i]);
}

// ------------------------- fold Wout into W2: Wc = W2 @ Wout ----------------
__global__ void wcombine_kernel(const float* __restrict__ W2, const float* __restrict__ Wout,
                                const float* __restrict__ b_out) {
    int idx = blockIdx.x * blockDim.x + threadIdx.x;
    if (idx >= OUTD * 64) return;
    int r = idx >> 6, k = idx & 63;
    float s = 0.f;
#pragma unroll 8
    for (int c = 0; c < 64; c++) s = fmaf(W2[r * 64 + c], Wout[c * 64 + k], s);
    g_Wc[r * 64 + k] = s;
    if (k == 0) {
        float sb = 0.f;
#pragma unroll 8
        for (int c = 0; c < 64; c++) sb = fmaf(W2[r * 64 + c], b_out[c], sb);
        g_bc[r] = sb;
    }
}

// ------------------------- GEMM (warp-per-2-rows) --------------------------
// Prefetch double-buffer only for CT<=3 (avoids reg blowup at KOUT=192).
template <int KOUT, int OST, bool BIAS>
__global__ void __launch_bounds__(256) rowgemm(const float* __restrict__ in,
                                               const float* __restrict__ W,
                                               const float* __restrict__ bias,
                                               float* __restrict__ out) {
    constexpr int CT = (KOUT + 31) / 32;
    constexpr bool PREF = (CT <= 3);
    __shared__ __align__(16) float xsh[16][64];
    int lane = threadIdx.x & 31;
    int warp = threadIdx.x >> 5;
    int row0 = blockIdx.x * 16;
    {
        int r = threadIdx.x >> 4, c4 = threadIdx.x & 15;
        *(float4*)&xsh[r][c4 * 4] = *(const float4*)&in[(row0 + r) * 64 + c4 * 4];
    }
    __syncthreads();

    int r0 = warp * 2;
    float acc[2][CT];
#pragma unroll
    for (int i = 0; i < 2; i++)
#pragma unroll
        for (int j = 0; j < CT; j++) acc[i][j] = 0.0f;

    float4 wb[CT];
    if (PREF) {
#pragma unroll
        for (int j = 0; j < CT; j++) {
            int c = lane + j * 32;
            wb[j] = ((KOUT & 31) == 0 || c < KOUT) ? *(const float4*)&W[c * 64]
                                                   : make_float4(0.f, 0.f, 0.f, 0.f);
        }
    }

#pragma unroll
    for (int k4 = 0; k4 < 16; k4++) {
        float4 wc[CT];
        if (PREF) {
#pragma unroll
            for (int j = 0; j < CT; j++) wc[j] = wb[j];
            if (k4 < 15) {
#pragma unroll
                for (int j = 0; j < CT; j++) {
                    int c = lane + j * 32;
                    wb[j] = ((KOUT & 31) == 0 || c < KOUT)
                                ? *(const float4*)&W[c * 64 + (k4 + 1) * 4]
                                : make_float4(0.f, 0.f, 0.f, 0.f);
                }
            }
        } else {
#pragma unroll
            for (int j = 0; j < CT; j++) {
                int c = lane + j * 32;
                wc[j] = ((KOUT & 31) == 0 || c < KOUT)
                            ? *(const float4*)&W[c * 64 + k4 * 4]
                            : make_float4(0.f, 0.f, 0.f, 0.f);
            }
        }
        float4 xa = *(const float4*)&xsh[r0][k4 * 4];
        float4 xb = *(const float4*)&xsh[r0 + 1][k4 * 4];
#pragma unroll
        for (int j = 0; j < CT; j++) {
            acc[0][j] = fmaf(xa.x, wc[j].x, acc[0][j]); acc[0][j] = fmaf(xa.y, wc[j].y, acc[0][j]);
            acc[0][j] = fmaf(xa.z, wc[j].z, acc[0][j]); acc[0][j] = fmaf(xa.w, wc[j].w, acc[0][j]);
            acc[1][j] = fmaf(xb.x, wc[j].x, acc[1][j]); acc[1][j] = fmaf(xb.y, wc[j].y, acc[1][j]);
            acc[1][j] = fmaf(xb.z, wc[j].z, acc[1][j]); acc[1][j] = fmaf(xb.w, wc[j].w, acc[1][j]);
        }
    }
#pragma unroll
    for (int i = 0; i < 2; i++) {
        int r = row0 + r0 + i;
#pragma unroll
        for (int j = 0; j < CT; j++) {
            int c = lane + j * 32;
            if ((KOUT & 31) == 0 || c < KOUT) {
                float v = acc[i][j];
                if (BIAS) v += bias[c];
                out[r * OST + c] = v;
            }
        }
    }
}

// ------------------------- GCN1 scatter: 16 lanes/edge, red.v4 -------------
__global__ void scatter64_kernel(const int* __restrict__ ei, const float* __restrict__ ea) {
    int gtid = blockIdx.x * blockDim.x + threadIdx.x;
    int e = gtid >> 4;
    if (e >= EE) return;
    int l16 = gtid & 15;
    int s = ei[e];
    int d = ei[EE + e];
    float coef = g_dis[s] * ea[e] * g_dis[d];
    float4 v = *(const float4*)&g_hw[s * 64 + l16 * 4];
    float* p = &g_agg1[d * 64 + l16 * 4];
    asm volatile("red.global.add.v4.f32 [%0], {%1,%2,%3,%4};"
                 :: "l"(p), "f"(coef * v.x), "f"(coef * v.y),
                    "f"(coef * v.z), "f"(coef * v.w) : "memory");
}

__global__ void post1_kernel(const float* __restrict__ b1) {
    int idx = blockIdx.x * blockDim.x + threadIdx.x;  // float4 units
    if (idx >= NN * 16) return;
    int i = idx >> 4, c4 = idx & 15;
    float di = g_dis[i];
    float d2 = di * di;
    float4 a = *(const float4*)&g_agg1[idx * 4];
    float4 hw = *(const float4*)&g_hw[idx * 4];
    float4 bb = *(const float4*)&b1[c4 * 4];
    float4 r;
    r.x = fmaxf(a.x + d2 * hw.x + bb.x, 0.f);
    r.y = fmaxf(a.y + d2 * hw.y + bb.y, 0.f);
    r.z = fmaxf(a.z + d2 * hw.z + bb.z, 0.f);
    r.w = fmaxf(a.w + d2 * hw.w + bb.w, 0.f);
    *(float4*)&g_h[idx * 4] = r;
}

// ------------------------- attention: fixed-base softmax, split-K ----------
// grid (NN/256, NHEADS, CHUNKS), block 128. Warp covers 64 queries
// (lane, lane+32); iterates its chunk's 512 keys via 64-key smem tiles.
__global__ void __launch_bounds__(128) attn_kernel() {
    int h = blockIdx.y, chunk = blockIdx.z;
    int lane = threadIdx.x & 31;
    int warp = threadIdx.x >> 5;
    int q0 = blockIdx.x * 256 + warp * 64 + lane;

    __shared__ __align__(16) float Ksh[64 * 16];
    __shared__ __align__(16) float Vsh[64 * 16];

    const float SC = 0.25f * 1.44269504088896f;  // (1/sqrt(dh)) * log2(e)
    ull q2[2][8];
#pragma unroll
    for (int qq = 0; qq < 2; qq++) {
        const float* qp = g_qkv + (q0 + qq * 32) * 192 + h * DH;
#pragma unroll
        for (int dp = 0; dp < 8; dp++)
            q2[qq][dp] = pk2(qp[2 * dp] * SC, qp[2 * dp + 1] * SC);
    }
    float l0 = 0.f, l1 = 0.f;
    ull acc[2][8];
#pragma unroll
    for (int qq = 0; qq < 2; qq++)
#pragma unroll
        for (int dp = 0; dp < 8; dp++) acc[qq][dp] = 0ull;

    for (int t = 0; t < CKEYS / 64; t++) {
        int key0 = chunk * CKEYS + t * 64;
        __syncthreads();
#pragma unroll
        for (int i = threadIdx.x; i < 256; i += 128) {
            int j = i >> 2, c4 = i & 3;
            const float* kb = g_qkv + (key0 + j) * 192 + 64 + h * DH + c4 * 4;
            *(float4*)&Ksh[j * 16 + c4 * 4] = *(const float4*)kb;
            *(float4*)&Vsh[j * 16 + c4 * 4] = *(const float4*)(kb + 64);
        }
        __syncthreads();

#pragma unroll 4
        for (int j = 0; j < 64; j++) {
            const ulonglong2* kr = (const ulonglong2*)&Ksh[j * 16];
            ulonglong2 ka = kr[0], kb = kr[1], kc = kr[2], kd = kr[3];
            float p0, p1;
            {
                ull s2 = mul2(q2[0][0], ka.x); s2 = fma2(q2[0][1], ka.y, s2);
                s2 = fma2(q2[0][2], kb.x, s2); s2 = fma2(q2[0][3], kb.y, s2);
                s2 = fma2(q2[0][4], kc.x, s2); s2 = fma2(q2[0][5], kc.y, s2);
                s2 = fma2(q2[0][6], kd.x, s2); s2 = fma2(q2[0][7], kd.y, s2);
                float lo, hi; upk2(s2, lo, hi);
                p0 = ex2(lo + hi);
            }
            {
                ull s2 = mul2(q2[1][0], ka.x); s2 = fma2(q2[1][1], ka.y, s2);
                s2 = fma2(q2[1][2], kb.x, s2); s2 = fma2(q2[1][3], kb.y, s2);
                s2 = fma2(q2[1][4], kc.x, s2); s2 = fma2(q2[1][5], kc.y, s2);
                s2 = fma2(q2[1][6], kd.x, s2); s2 = fma2(q2[1][7], kd.y, s2);
                float lo, hi; upk2(s2, lo, hi);
                p1 = ex2(lo + hi);
            }
            l0 += p0; l1 += p1;
            ull pp0 = pk2(p0, p0), pp1 = pk2(p1, p1);
            const ulonglong2* vr = (const ulonglong2*)&Vsh[j * 16];
            ulonglong2 va = vr[0], vb = vr[1], vc = vr[2], vd = vr[3];
            acc[0][0] = fma2(pp0, va.x, acc[0][0]); acc[0][1] = fma2(pp0, va.y, acc[0][1]);
            acc[0][2] = fma2(pp0, vb.x, acc[0][2]); acc[0][3] = fma2(pp0, vb.y, acc[0][3]);
            acc[0][4] = fma2(pp0, vc.x, acc[0][4]); acc[0][5] = fma2(pp0, vc.y, acc[0][5]);
            acc[0][6] = fma2(pp0, vd.x, acc[0][6]); acc[0][7] = fma2(pp0, vd.y, acc[0][7]);
            acc[1][0] = fma2(pp1, va.x, acc[1][0]); acc[1][1] = fma2(pp1, va.y, acc[1][1]);
            acc[1][2] = fma2(pp1, vb.x, acc[1][2]); acc[1][3] = fma2(pp1, vb.y, acc[1][3]);
            acc[1][4] = fma2(pp1, vc.x, acc[1][4]); acc[1][5] = fma2(pp1, vc.y, acc[1][5]);
            acc[1][6] = fma2(pp1, vd.x, acc[1][6]); acc[1][7] = fma2(pp1, vd.y, acc[1][7]);
        }
    }

#pragma unroll
    for (int qq = 0; qq < 2; qq++) {
        int q = q0 + qq * 32;
        size_t idx = ((size_t)(h * CHUNKS + chunk)) * NN + q;
        g_pl[idx] = (qq == 0) ? l0 : l1;
        ulonglong2* row = (ulonglong2*)&g_pacc[idx * DH];
#pragma unroll
        for (int d4 = 0; d4 < 4; d4++) {
            ulonglong2 w2;
            w2.x = acc[qq][d4 * 2]; w2.y = acc[qq][d4 * 2 + 1];
            row[d4] = w2;
        }
    }
}

__global__ void attn_combine() {
    int t = blockIdx.x * blockDim.x + threadIdx.x;
    if (t >= NHEADS * NN) return;
    int h = t >> 12, q = t & (NN - 1);
    float l = 0.f;
    float o[16];
#pragma unroll
    for (int d = 0; d < 16; d++) o[d] = 0.f;
#pragma unroll
    for (int c = 0; c < CHUNKS; c++) {
        size_t idx = ((size_t)(h * CHUNKS + c)) * NN + q;
        l += g_pl[idx];
        const float4* row = (const float4*)&g_pacc[idx * DH];
#pragma unroll
        for (int d4 = 0; d4 < 4; d4++) {
            float4 a = row[d4];
            o[d4 * 4 + 0] += a.x; o[d4 * 4 + 1] += a.y;
            o[d4 * 4 + 2] += a.z; o[d4 * 4 + 3] += a.w;
        }
    }
    float inv = 1.0f / l;
    float* op = g_o + q * 64 + h * DH;
#pragma unroll
    for (int d = 0; d < 16; d++) op[d] = o[d] * inv;
}

// ------------------------- GCN2 scatter: warp/edge, 22 v4 lanes ------------
__global__ void scatter88_kernel(const int* __restrict__ ei, const float* __restrict__ ea) {
    int gtid = blockIdx.x * blockDim.x + threadIdx.x;
    int e = gtid >> 5;
    if (e >= EE) return;
    int lane = gtid & 31;
    if (lane >= 22) return;
    int s = ei[e];
    int d = ei[EE + e];
    float coef = g_dis[s] * ea[e] * g_dis[d];
    float4 v = *(const float4*)&g_h2w[s * OUTP + lane * 4];
    float* p = &g_agg2[d * OUTP + lane * 4];
    asm volatile("red.global.add.v4.f32 [%0], {%1,%2,%3,%4};"
                 :: "l"(p), "f"(coef * v.x), "f"(coef * v.y),
                    "f"(coef * v.z), "f"(coef * v.w) : "memory");
}

__global__ void final_node_kernel(const int* __restrict__ batch, const float* __restrict__ b2) {
    int idx = blockIdx.x * blockDim.x + threadIdx.x;
    if (idx >= NN * OUTP) return;
    int i = idx / OUTP, f = idx - i * OUTP;
    if (f >= OUTD) return;
    float di = g_dis[i];
    float v = g_agg2[idx] + di * di * g_h2w[idx] + b2[f];
    atomicAdd(&g_pool[batch[i] * OUTD + f], v);
}

__global__ void out_kernel(float* __restrict__ out) {
    int idx = blockIdx.x * blockDim.x + threadIdx.x;
    if (idx >= BB * OUTD) return;
    int b = idx / OUTD;
    out[idx] = g_pool[idx] / fmaxf(g_cnt[b], 1.0f);
}

// ------------------------- launch ------------------------------------------
extern "C" void kernel_launch(void* const* d_in, const int* in_sizes, int n_in,
                              void* d_out, int out_size) {
    const float* x     = (const float*)d_in[0];
    const int*   ei    = (const int*)  d_in[1];
    const float* ea    = (const float*)d_in[2];
    const int*   batch = (const int*)  d_in[3];
    const float* W1    = (const float*)d_in[4];
    const float* b1    = (const float*)d_in[5];
    const float* Win   = (const float*)d_in[6];
    const float* b_in  = (const float*)d_in[7];
    const float* Wout  = (const float*)d_in[8];
    const float* b_out = (const float*)d_in[9];
    const float* W2    = (const float*)d_in[10];
    const float* b2    = (const float*)d_in[11];
    float* out = (float*)d_out;

    float *p_hw, *p_h, *p_qkv, *p_o, *p_h2w, *p_Wc, *p_bc;
    cudaGetSymbolAddress((void**)&p_hw,  g_hw);
    cudaGetSymbolAddress((void**)&p_h,   g_h);
    cudaGetSymbolAddress((void**)&p_qkv, g_qkv);
    cudaGetSymbolAddress((void**)&p_o,   g_o);
    cudaGetSymbolAddress((void**)&p_h2w, g_h2w);
    cudaGetSymbolAddress((void**)&p_Wc,  g_Wc);
    cudaGetSymbolAddress((void**)&p_bc,  g_bc);

    // 1. init + folded weight (independent of graph data)
    init_kernel<<<(NN * OUTP + 255) / 256, 256>>>();
    wcombine_kernel<<<(OUTD * 64 + 255) / 256, 256>>>(W2, Wout, b_out);
    // 2. degree + batch counts + norm
    accum_kernel<<<EE / 256, 256>>>(ei, ea, batch);
    dis_kernel<<<NN / 256, 256>>>();
    // 3. GCN1 linear + aggregate + post
    rowgemm<64, 64, false><<<NN / 16, 256>>>(x, W1, nullptr, p_hw);
    scatter64_kernel<<<EE * 16 / 256, 256>>>(ei, ea);
    post1_kernel<<<NN * 16 / 256, 256>>>(b1);
    // 4. QKV projection
    rowgemm<192, 192, true><<<NN / 16, 256>>>(p_h, Win, b_in, p_qkv);
    // 5. attention (split-K partials + combine)
    attn_kernel<<<dim3(NN / 256, NHEADS, CHUNKS), 128>>>();
    attn_combine<<<(NHEADS * NN) / 256, 256>>>();
    // 6. fused (Wout∘W2) linear
    rowgemm<86, 88, true><<<NN / 16, 256>>>(p_o, p_Wc, p_bc, p_h2w);
    // 7. GCN2 aggregate + pool
    scatter88_kernel<<<EE * 32 / 256, 256>>>(ei, ea);
    final_node_kernel<<<(NN * OUTP + 255) / 256, 256>>>(batch, b2);
    out_kernel<<<(BB * OUTD + 255) / 256, 256>>>(out);
}

// round 7
// speedup vs baseline: 1.6113x; 1.0649x over previous
#include <cuda_runtime.h>
#include <math.h>

#define NN 4096
#define EE 131072
#define HIDD 64
#define OUTD 86
#define OUTP 88
#define BB 16
#define NHEADS 4
#define DH 16
#define CHUNKS 16
#define CKEYS (NN / CHUNKS)   // 256 keys per chunk

typedef unsigned long long ull;

// ------------------------- f32x2 packed helpers ----------------------------
__device__ __forceinline__ ull pk2(float lo, float hi) {
    ull r; asm("mov.b64 %0,{%1,%2};" : "=l"(r) : "f"(lo), "f"(hi)); return r;
}
__device__ __forceinline__ void upk2(ull v, float& lo, float& hi) {
    asm("mov.b64 {%0,%1},%2;" : "=f"(lo), "=f"(hi) : "l"(v));
}
__device__ __forceinline__ ull fma2(ull a, ull b, ull c) {
    ull d; asm("fma.rn.f32x2 %0,%1,%2,%3;" : "=l"(d) : "l"(a), "l"(b), "l"(c)); return d;
}
__device__ __forceinline__ ull mul2(ull a, ull b) {
    ull d; asm("mul.rn.f32x2 %0,%1,%2;" : "=l"(d) : "l"(a), "l"(b)); return d;
}
__device__ __forceinline__ float ex2(float x) {
    float y; asm("ex2.approx.ftz.f32 %0,%1;" : "=f"(y) : "f"(x)); return y;
}

// ------------------------- scratch -----------------------------------------
__device__ float g_deg[NN];
__device__ float g_hw[NN * HIDD];
__device__ float g_agg1[NN * HIDD];
__device__ float g_qkv[NN * 3 * HIDD];
__device__ float g_h2w[NN * OUTP];
__device__ float g_agg2[NN * OUTP];
__device__ float g_pool[BB * OUTD];
__device__ float g_cnt[BB];
__device__ float g_pl[NHEADS * CHUNKS * NN];
__device__ float g_pacc[NHEADS * CHUNKS * NN * DH];
__device__ float g_Wc[OUTD * 64];
__device__ float g_bc[OUTD];

// ------------------------- prep: zero + folded weight ----------------------
__global__ void prep_kernel(const float* __restrict__ W2, const float* __restrict__ Wout,
                            const float* __restrict__ b_out) {
    int idx = blockIdx.x * blockDim.x + threadIdx.x;
    if (idx < NN * HIDD) g_agg1[idx] = 0.0f;
    if (idx < NN * OUTP) g_agg2[idx] = 0.0f;
    if (idx < BB * OUTD) g_pool[idx] = 0.0f;
    if (idx < BB) g_cnt[idx] = 0.0f;
    if (idx < NN) g_deg[idx] = 1.0f;   // self-loop weight 1
    if (idx < OUTD * 64) {             // Wc = W2 @ Wout ; bc = W2 @ b_out
        int r = idx >> 6, k = idx & 63;
        float s = 0.f;
#pragma unroll 8
        for (int c = 0; c < 64; c++) s = fmaf(W2[r * 64 + c], Wout[c * 64 + k], s);
        g_Wc[r * 64 + k] = s;
        if (k == 0) {
            float sb = 0.f;
#pragma unroll 8
            for (int c = 0; c < 64; c++) sb = fmaf(W2[r * 64 + c], b_out[c], sb);
            g_bc[r] = sb;
        }
    }
}

__global__ void accum_kernel(const int* __restrict__ ei, const float* __restrict__ ea,
                             const int* __restrict__ batch) {
    int e = blockIdx.x * blockDim.x + threadIdx.x;
    if (e < EE) atomicAdd(&g_deg[ei[EE + e]], ea[e]);
    if (e < NN) atomicAdd(&g_cnt[batch[e]], 1.0f);
}

// ------------------------- GEMM (warp-per-2-rows, prefetch) -----------------
// MODE 0: plain input, 1: fused GCN1-post (agg1/hw -> relu), 2: fused attn-combine
template <int KOUT, int OST, bool BIAS, int MODE>
__global__ void __launch_bounds__(256) rowgemm(const float* __restrict__ in,
                                               const float* __restrict__ W,
                                               const float* __restrict__ bias,
                                               const float* __restrict__ inb,
                                               float* __restrict__ out) {
    constexpr int CT = (KOUT + 31) / 32;
    __shared__ __align__(16) float xsh[16][64];
    int lane = threadIdx.x & 31;
    int warp = threadIdx.x >> 5;
    int row0 = blockIdx.x * 16;
    {
        int r = threadIdx.x >> 4, c4 = threadIdx.x & 15;
        int row = row0 + r;
        if (MODE == 0) {
            *(float4*)&xsh[r][c4 * 4] = *(const float4*)&in[row * 64 + c4 * 4];
        } else if (MODE == 1) {
            float d2 = __frcp_rn(g_deg[row]);   // dis^2 == 1/deg
            float4 a  = *(const float4*)&g_agg1[row * 64 + c4 * 4];
            float4 hw = *(const float4*)&g_hw[row * 64 + c4 * 4];
            float4 bb = *(const float4*)&inb[c4 * 4];
            float4 v;
            v.x = fmaxf(fmaf(d2, hw.x, a.x) + bb.x, 0.f);
            v.y = fmaxf(fmaf(d2, hw.y, a.y) + bb.y, 0.f);
            v.z = fmaxf(fmaf(d2, hw.z, a.z) + bb.z, 0.f);
            v.w = fmaxf(fmaf(d2, hw.w, a.w) + bb.w, 0.f);
            *(float4*)&xsh[r][c4 * 4] = v;
        } else {
            // attention combine: head h = c4>>2, dims d0..d0+3 of that head
            int h = c4 >> 2, d0 = (c4 & 3) * 4;
            float l = 0.f;
            float4 o = make_float4(0.f, 0.f, 0.f, 0.f);
#pragma unroll
            for (int c = 0; c < CHUNKS; c++) {
                size_t idx = ((size_t)(h * CHUNKS + c)) * NN + row;
                l += g_pl[idx];
                float4 a = *(const float4*)&g_pacc[idx * DH + d0];
                o.x += a.x; o.y += a.y; o.z += a.z; o.w += a.w;
            }
            float inv = 1.0f / l;
            o.x *= inv; o.y *= inv; o.z *= inv; o.w *= inv;
            *(float4*)&xsh[r][c4 * 4] = o;
        }
    }
    __syncthreads();

    int r0 = warp * 2;
    float acc[2][CT];
#pragma unroll
    for (int i = 0; i < 2; i++)
#pragma unroll
        for (int j = 0; j < CT; j++) acc[i][j] = 0.0f;

    float4 wb[CT];
#pragma unroll
    for (int j = 0; j < CT; j++) {
        int c = lane + j * 32;
        wb[j] = ((KOUT & 31) == 0 || c < KOUT) ? *(const float4*)&W[c * 64]
                                               : make_float4(0.f, 0.f, 0.f, 0.f);
    }

#pragma unroll
    for (int k4 = 0; k4 < 16; k4++) {
        float4 wc[CT];
#pragma unroll
        for (int j = 0; j < CT; j++) wc[j] = wb[j];
        if (k4 < 15) {
#pragma unroll
            for (int j = 0; j < CT; j++) {
                int c = lane + j * 32;
                wb[j] = ((KOUT & 31) == 0 || c < KOUT)
                            ? *(const float4*)&W[c * 64 + (k4 + 1) * 4]
                            : make_float4(0.f, 0.f, 0.f, 0.f);
            }
        }
        float4 xa = *(const float4*)&xsh[r0][k4 * 4];
        float4 xb = *(const float4*)&xsh[r0 + 1][k4 * 4];
#pragma unroll
        for (int j = 0; j < CT; j++) {
            acc[0][j] = fmaf(xa.x, wc[j].x, acc[0][j]); acc[0][j] = fmaf(xa.y, wc[j].y, acc[0][j]);
            acc[0][j] = fmaf(xa.z, wc[j].z, acc[0][j]); acc[0][j] = fmaf(xa.w, wc[j].w, acc[0][j]);
            acc[1][j] = fmaf(xb.x, wc[j].x, acc[1][j]); acc[1][j] = fmaf(xb.y, wc[j].y, acc[1][j]);
            acc[1][j] = fmaf(xb.z, wc[j].z, acc[1][j]); acc[1][j] = fmaf(xb.w, wc[j].w, acc[1][j]);
        }
    }
#pragma unroll
    for (int i = 0; i < 2; i++) {
        int r = row0 + r0 + i;
#pragma unroll
        for (int j = 0; j < CT; j++) {
            int c = lane + j * 32;
            if ((KOUT & 31) == 0 || c < KOUT) {
                float v = acc[i][j];
                if (BIAS) v += bias[c];
                out[r * OST + c] = v;
            }
        }
    }
}

// ------------------------- GCN1 scatter: 16 lanes/edge, red.v4 -------------
__global__ void scatter64_kernel(const int* __restrict__ ei, const float* __restrict__ ea) {
    int gtid = blockIdx.x * blockDim.x + threadIdx.x;
    int e = gtid >> 4;
    if (e >= EE) return;
    int l16 = gtid & 15;
    int s = ei[e];
    int d = ei[EE + e];
    float coef = rsqrtf(g_deg[s]) * ea[e] * rsqrtf(g_deg[d]);
    float4 v = *(const float4*)&g_hw[s * 64 + l16 * 4];
    float* p = &g_agg1[d * 64 + l16 * 4];
    asm volatile("red.global.add.v4.f32 [%0], {%1,%2,%3,%4};"
                 :: "l"(p), "f"(coef * v.x), "f"(coef * v.y),
                    "f"(coef * v.z), "f"(coef * v.w) : "memory");
}

// ------------------------- attention: fixed-base softmax, split-K ----------
// grid (NN/256, NHEADS, CHUNKS), block 128. Warp covers 64 queries
// (lane, lane+32); iterates its chunk's 256 keys via 64-key smem tiles.
__global__ void __launch_bounds__(128) attn_kernel() {
    int h = blockIdx.y, chunk = blockIdx.z;
    int lane = threadIdx.x & 31;
    int warp = threadIdx.x >> 5;
    int q0 = blockIdx.x * 256 + warp * 64 + lane;

    __shared__ __align__(16) float Ksh[64 * 16];
    __shared__ __align__(16) float Vsh[64 * 16];

    const float SC = 0.25f * 1.44269504088896f;  // (1/sqrt(dh)) * log2(e)
    ull q2[2][8];
#pragma unroll
    for (int qq = 0; qq < 2; qq++) {
        const float* qp = g_qkv + (q0 + qq * 32) * 192 + h * DH;
#pragma unroll
        for (int dp = 0; dp < 8; dp++)
            q2[qq][dp] = pk2(qp[2 * dp] * SC, qp[2 * dp + 1] * SC);
    }
    float l0 = 0.f, l1 = 0.f;
    ull acc[2][8];
#pragma unroll
    for (int qq = 0; qq < 2; qq++)
#pragma unroll
        for (int dp = 0; dp < 8; dp++) acc[qq][dp] = 0ull;

    for (int t = 0; t < CKEYS / 64; t++) {
        int key0 = chunk * CKEYS + t * 64;
        __syncthreads();
#pragma unroll
        for (int i = threadIdx.x; i < 256; i += 128) {
            int j = i >> 2, c4 = i & 3;
            const float* kb = g_qkv + (key0 + j) * 192 + 64 + h * DH + c4 * 4;
            *(float4*)&Ksh[j * 16 + c4 * 4] = *(const float4*)kb;
            *(float4*)&Vsh[j * 16 + c4 * 4] = *(const float4*)(kb + 64);
        }
        __syncthreads();

#pragma unroll 4
        for (int j = 0; j < 64; j++) {
            const ulonglong2* kr = (const ulonglong2*)&Ksh[j * 16];
            ulonglong2 ka = kr[0], kb = kr[1], kc = kr[2], kd = kr[3];
            float p0, p1;
            {
                ull s2 = mul2(q2[0][0], ka.x); s2 = fma2(q2[0][1], ka.y, s2);
                s2 = fma2(q2[0][2], kb.x, s2); s2 = fma2(q2[0][3], kb.y, s2);
                s2 = fma2(q2[0][4], kc.x, s2); s2 = fma2(q2[0][5], kc.y, s2);
                s2 = fma2(q2[0][6], kd.x, s2); s2 = fma2(q2[0][7], kd.y, s2);
                float lo, hi; upk2(s2, lo, hi);
                p0 = ex2(lo + hi);
            }
            {
                ull s2 = mul2(q2[1][0], ka.x); s2 = fma2(q2[1][1], ka.y, s2);
                s2 = fma2(q2[1][2], kb.x, s2); s2 = fma2(q2[1][3], kb.y, s2);
                s2 = fma2(q2[1][4], kc.x, s2); s2 = fma2(q2[1][5], kc.y, s2);
                s2 = fma2(q2[1][6], kd.x, s2); s2 = fma2(q2[1][7], kd.y, s2);
                float lo, hi; upk2(s2, lo, hi);
                p1 = ex2(lo + hi);
            }
            l0 += p0; l1 += p1;
            ull pp0 = pk2(p0, p0), pp1 = pk2(p1, p1);
            const ulonglong2* vr = (const ulonglong2*)&Vsh[j * 16];
            ulonglong2 va = vr[0], vb = vr[1], vc = vr[2], vd = vr[3];
            acc[0][0] = fma2(pp0, va.x, acc[0][0]); acc[0][1] = fma2(pp0, va.y, acc[0][1]);
            acc[0][2] = fma2(pp0, vb.x, acc[0][2]); acc[0][3] = fma2(pp0, vb.y, acc[0][3]);
            acc[0][4] = fma2(pp0, vc.x, acc[0][4]); acc[0][5] = fma2(pp0, vc.y, acc[0][5]);
            acc[0][6] = fma2(pp0, vd.x, acc[0][6]); acc[0][7] = fma2(pp0, vd.y, acc[0][7]);
            acc[1][0] = fma2(pp1, va.x, acc[1][0]); acc[1][1] = fma2(pp1, va.y, acc[1][1]);
            acc[1][2] = fma2(pp1, vb.x, acc[1][2]); acc[1][3] = fma2(pp1, vb.y, acc[1][3]);
            acc[1][4] = fma2(pp1, vc.x, acc[1][4]); acc[1][5] = fma2(pp1, vc.y, acc[1][5]);
            acc[1][6] = fma2(pp1, vd.x, acc[1][6]); acc[1][7] = fma2(pp1, vd.y, acc[1][7]);
        }
    }

#pragma unroll
    for (int qq = 0; qq < 2; qq++) {
        int q = q0 + qq * 32;
        size_t idx = ((size_t)(h * CHUNKS + chunk)) * NN + q;
        g_pl[idx] = (qq == 0) ? l0 : l1;
        ulonglong2* row = (ulonglong2*)&g_pacc[idx * DH];
#pragma unroll
        for (int d4 = 0; d4 < 4; d4++) {
            ulonglong2 w2;
            w2.x = acc[qq][d4 * 2]; w2.y = acc[qq][d4 * 2 + 1];
            row[d4] = w2;
        }
    }
}

// ------------------------- GCN2 scatter: warp/edge, 22 v4 lanes ------------
__global__ void scatter88_kernel(const int* __restrict__ ei, const float* __restrict__ ea) {
    int gtid = blockIdx.x * blockDim.x + threadIdx.x;
    int e = gtid >> 5;
    if (e >= EE) return;
    int lane = gtid & 31;
    if (lane >= 22) return;
    int s = ei[e];
    int d = ei[EE + e];
    float coef = rsqrtf(g_deg[s]) * ea[e] * rsqrtf(g_deg[d]);
    float4 v = *(const float4*)&g_h2w[s * OUTP + lane * 4];
    float* p = &g_agg2[d * OUTP + lane * 4];
    asm volatile("red.global.add.v4.f32 [%0], {%1,%2,%3,%4};"
                 :: "l"(p), "f"(coef * v.x), "f"(coef * v.y),
                    "f"(coef * v.z), "f"(coef * v.w) : "memory");
}

__global__ void final_node_kernel(const int* __restrict__ batch, const float* __restrict__ b2) {
    int idx = blockIdx.x * blockDim.x + threadIdx.x;
    if (idx >= NN * OUTP) return;
    int i = idx / OUTP, f = idx - i * OUTP;
    if (f >= OUTD) return;
    float d2 = __frcp_rn(g_deg[i]);
    float v = g_agg2[idx] + d2 * g_h2w[idx] + b2[f];
    atomicAdd(&g_pool[batch[i] * OUTD + f], v);
}

__global__ void out_kernel(float* __restrict__ out) {
    int idx = blockIdx.x * blockDim.x + threadIdx.x;
    if (idx >= BB * OUTD) return;
    int b = idx / OUTD;
    out[idx] = g_pool[idx] / fmaxf(g_cnt[b], 1.0f);
}

// ------------------------- launch ------------------------------------------
extern "C" void kernel_launch(void* const* d_in, const int* in_sizes, int n_in,
                              void* d_out, int out_size) {
    const float* x     = (const float*)d_in[0];
    const int*   ei    = (const int*)  d_in[1];
    const float* ea    = (const float*)d_in[2];
    const int*   batch = (const int*)  d_in[3];
    const float* W1    = (const float*)d_in[4];
    const float* b1    = (const float*)d_in[5];
    const float* Win   = (const float*)d_in[6];
    const float* b_in  = (const float*)d_in[7];
    const float* Wout  = (const float*)d_in[8];
    const float* b_out = (const float*)d_in[9];
    const float* W2    = (const float*)d_in[10];
    const float* b2    = (const float*)d_in[11];
    float* out = (float*)d_out;

    float *p_hw, *p_qkv, *p_h2w, *p_Wc, *p_bc;
    cudaGetSymbolAddress((void**)&p_hw,  g_hw);
    cudaGetSymbolAddress((void**)&p_qkv, g_qkv);
    cudaGetSymbolAddress((void**)&p_h2w, g_h2w);
    cudaGetSymbolAddress((void**)&p_Wc,  g_Wc);
    cudaGetSymbolAddress((void**)&p_bc,  g_bc);

    // 0. prep: zero accumulators + fold Wout into W2
    prep_kernel<<<(NN * OUTP + 255) / 256, 256>>>(W2, Wout, b_out);
    // 1. GCN1 linear (independent of graph prep)
    rowgemm<64, 64, false, 0><<<NN / 16, 256>>>(x, W1, nullptr, nullptr, p_hw);
    // 2. degree + batch counts
    accum_kernel<<<EE / 256, 256>>>(ei, ea, batch);
    // 3. GCN1 aggregate (inline rsqrt norm)
    scatter64_kernel<<<EE * 16 / 256, 256>>>(ei, ea);
    // 4. QKV projection with fused GCN1 post (relu(agg + hw/deg + b1))
    rowgemm<192, 192, true, 1><<<NN / 16, 256>>>(nullptr, Win, b_in, b1, p_qkv);
    // 5. attention (split-K partials)
    attn_kernel<<<dim3(NN / 256, NHEADS, CHUNKS), 128>>>();
    // 6. fused (Wout∘W2) linear with fused attention combine
    rowgemm<86, 88, true, 2><<<NN / 16, 256>>>(nullptr, p_Wc, p_bc, nullptr, p_h2w);
    // 7. GCN2 aggregate + pool
    scatter88_kernel<<<EE * 32 / 256, 256>>>(ei, ea);
    final_node_kernel<<<(NN * OUTP + 255) / 256, 256>>>(batch, b2);
    out_kernel<<<(BB * OUTD + 255) / 256, 256>>>(out);
}

// round 8
// speedup vs baseline: 2.7219x; 1.6893x over previous
#include <cuda_runtime.h>
#include <cuda_bf16.h>
#include <math.h>

#define NN 4096
#define EE 131072
#define HIDD 64
#define OUTD 86
#define OUTP 88
#define BB 16
#define NHEADS 4
#define DH 16
#define CHUNKS 4
#define CKEYS (NN / CHUNKS)   // 1024 keys per chunk
#define KT 128                // keys per smem tile

typedef unsigned int uint32;

__device__ __forceinline__ float ex2(float x) {
    float y; asm("ex2.approx.ftz.f32 %0,%1;" : "=f"(y) : "f"(x)); return y;
}
// pack two f32 -> bf16x2 (lo = first arg)
__device__ __forceinline__ uint32 packbf(float lo, float hi) {
    uint32 r; asm("cvt.rn.bf16x2.f32 %0, %1, %2;" : "=r"(r) : "f"(hi), "f"(lo)); return r;
}
__device__ __forceinline__ void mma16816(float* d, const uint32* a, uint32 b0, uint32 b1,
                                         const float* c) {
    asm("mma.sync.aligned.m16n8k16.row.col.f32.bf16.bf16.f32 "
        "{%0,%1,%2,%3},{%4,%5,%6,%7},{%8,%9},{%10,%11,%12,%13};"
        : "=f"(d[0]), "=f"(d[1]), "=f"(d[2]), "=f"(d[3])
        : "r"(a[0]), "r"(a[1]), "r"(a[2]), "r"(a[3]), "r"(b0), "r"(b1),
          "f"(c[0]), "f"(c[1]), "f"(c[2]), "f"(c[3]));
}

// ------------------------- scratch -----------------------------------------
__device__ float g_deg[NN];
__device__ float g_hw[NN * HIDD];
__device__ float g_agg1[NN * HIDD];
__device__ float g_qkv[NN * 3 * HIDD];
__device__ float g_h2w[NN * OUTP];
__device__ float g_agg2[NN * OUTP];
__device__ float g_pool[BB * OUTD];
__device__ float g_cnt[BB];
__device__ float g_pl[NHEADS * CHUNKS * NN];
__device__ float g_pacc[NHEADS * CHUNKS * NN * DH];
__device__ float g_Wc[OUTD * 64];
__device__ float g_bc[OUTD];

// ------------------------- prep: zero + folded weight ----------------------
__global__ void prep_kernel(const float* __restrict__ W2, const float* __restrict__ Wout,
                            const float* __restrict__ b_out) {
    int idx = blockIdx.x * blockDim.x + threadIdx.x;
    if (idx < NN * HIDD) g_agg1[idx] = 0.0f;
    if (idx < NN * OUTP) g_agg2[idx] = 0.0f;
    if (idx < BB * OUTD) g_pool[idx] = 0.0f;
    if (idx < BB) g_cnt[idx] = 0.0f;
    if (idx < NN) g_deg[idx] = 1.0f;   // self-loop weight 1
    if (idx < OUTD * 64) {             // Wc = W2 @ Wout ; bc = W2 @ b_out
        int r = idx >> 6, k = idx & 63;
        float s = 0.f;
#pragma unroll 8
        for (int c = 0; c < 64; c++) s = fmaf(W2[r * 64 + c], Wout[c * 64 + k], s);
        g_Wc[r * 64 + k] = s;
        if (k == 0) {
            float sb = 0.f;
#pragma unroll 8
            for (int c = 0; c < 64; c++) sb = fmaf(W2[r * 64 + c], b_out[c], sb);
            g_bc[r] = sb;
        }
    }
}

__global__ void accum_kernel(const int* __restrict__ ei, const float* __restrict__ ea,
                             const int* __restrict__ batch) {
    int e = blockIdx.x * blockDim.x + threadIdx.x;
    if (e < EE) atomicAdd(&g_deg[ei[EE + e]], ea[e]);
    if (e < NN) atomicAdd(&g_cnt[batch[e]], 1.0f);
}

// ------------------------- GEMM (warp-per-2-rows, prefetch) -----------------
// MODE 0: plain input, 1: fused GCN1-post, 2: fused attn-combine
template <int KOUT, int OST, bool BIAS, int MODE>
__global__ void __launch_bounds__(256) rowgemm(const float* __restrict__ in,
                                               const float* __restrict__ W,
                                               const float* __restrict__ bias,
                                               const float* __restrict__ inb,
                                               float* __restrict__ out) {
    constexpr int CT = (KOUT + 31) / 32;
    __shared__ __align__(16) float xsh[16][64];
    int lane = threadIdx.x & 31;
    int warp = threadIdx.x >> 5;
    int row0 = blockIdx.x * 16;
    {
        int r = threadIdx.x >> 4, c4 = threadIdx.x & 15;
        int row = row0 + r;
        if (MODE == 0) {
            *(float4*)&xsh[r][c4 * 4] = *(const float4*)&in[row * 64 + c4 * 4];
        } else if (MODE == 1) {
            float d2 = __frcp_rn(g_deg[row]);
            float4 a  = *(const float4*)&g_agg1[row * 64 + c4 * 4];
            float4 hw = *(const float4*)&g_hw[row * 64 + c4 * 4];
            float4 bb = *(const float4*)&inb[c4 * 4];
            float4 v;
            v.x = fmaxf(fmaf(d2, hw.x, a.x) + bb.x, 0.f);
            v.y = fmaxf(fmaf(d2, hw.y, a.y) + bb.y, 0.f);
            v.z = fmaxf(fmaf(d2, hw.z, a.z) + bb.z, 0.f);
            v.w = fmaxf(fmaf(d2, hw.w, a.w) + bb.w, 0.f);
            *(float4*)&xsh[r][c4 * 4] = v;
        } else {
            int h = c4 >> 2, d0 = (c4 & 3) * 4;
            float l = 0.f;
            float4 o = make_float4(0.f, 0.f, 0.f, 0.f);
#pragma unroll
            for (int c = 0; c < CHUNKS; c++) {
                size_t idx = ((size_t)(h * CHUNKS + c)) * NN + row;
                l += g_pl[idx];
                float4 a = *(const float4*)&g_pacc[idx * DH + d0];
                o.x += a.x; o.y += a.y; o.z += a.z; o.w += a.w;
            }
            float inv = 1.0f / l;
            o.x *= inv; o.y *= inv; o.z *= inv; o.w *= inv;
            *(float4*)&xsh[r][c4 * 4] = o;
        }
    }
    __syncthreads();

    int r0 = warp * 2;
    float acc[2][CT];
#pragma unroll
    for (int i = 0; i < 2; i++)
#pragma unroll
        for (int j = 0; j < CT; j++) acc[i][j] = 0.0f;

    float4 wb[CT];
#pragma unroll
    for (int j = 0; j < CT; j++) {
        int c = lane + j * 32;
        wb[j] = ((KOUT & 31) == 0 || c < KOUT) ? *(const float4*)&W[c * 64]
                                               : make_float4(0.f, 0.f, 0.f, 0.f);
    }

#pragma unroll
    for (int k4 = 0; k4 < 16; k4++) {
        float4 wc[CT];
#pragma unroll
        for (int j = 0; j < CT; j++) wc[j] = wb[j];
        if (k4 < 15) {
#pragma unroll
            for (int j = 0; j < CT; j++) {
                int c = lane + j * 32;
                wb[j] = ((KOUT & 31) == 0 || c < KOUT)
                            ? *(const float4*)&W[c * 64 + (k4 + 1) * 4]
                            : make_float4(0.f, 0.f, 0.f, 0.f);
            }
        }
        float4 xa = *(const float4*)&xsh[r0][k4 * 4];
        float4 xb = *(const float4*)&xsh[r0 + 1][k4 * 4];
#pragma unroll
        for (int j = 0; j < CT; j++) {
            acc[0][j] = fmaf(xa.x, wc[j].x, acc[0][j]); acc[0][j] = fmaf(xa.y, wc[j].y, acc[0][j]);
            acc[0][j] = fmaf(xa.z, wc[j].z, acc[0][j]); acc[0][j] = fmaf(xa.w, wc[j].w, acc[0][j]);
            acc[1][j] = fmaf(xb.x, wc[j].x, acc[1][j]); acc[1][j] = fmaf(xb.y, wc[j].y, acc[1][j]);
            acc[1][j] = fmaf(xb.z, wc[j].z, acc[1][j]); acc[1][j] = fmaf(xb.w, wc[j].w, acc[1][j]);
        }
    }
#pragma unroll
    for (int i = 0; i < 2; i++) {
        int r = row0 + r0 + i;
#pragma unroll
        for (int j = 0; j < CT; j++) {
            int c = lane + j * 32;
            if ((KOUT & 31) == 0 || c < KOUT) {
                float v = acc[i][j];
                if (BIAS) v += bias[c];
                out[r * OST + c] = v;
            }
        }
    }
}

// ------------------------- GCN1 scatter: 16 lanes/edge, red.v4 -------------
__global__ void scatter64_kernel(const int* __restrict__ ei, const float* __restrict__ ea) {
    int gtid = blockIdx.x * blockDim.x + threadIdx.x;
    int e = gtid >> 4;
    if (e >= EE) return;
    int l16 = gtid & 15;
    int s = ei[e];
    int d = ei[EE + e];
    float coef = rsqrtf(g_deg[s]) * ea[e] * rsqrtf(g_deg[d]);
    float4 v = *(const float4*)&g_hw[s * 64 + l16 * 4];
    float* p = &g_agg1[d * 64 + l16 * 4];
    asm volatile("red.global.add.v4.f32 [%0], {%1,%2,%3,%4};"
                 :: "l"(p), "f"(coef * v.x), "f"(coef * v.y),
                    "f"(coef * v.z), "f"(coef * v.w) : "memory");
}

// ------------------------- attention: mma.sync bf16, split-K ---------------
// grid (NN/128, NHEADS, CHUNKS), block 256 (8 warps). Each warp owns a 16-query
// tile; block shares 128-key K/V staging. Fixed-base softmax (no max).
__global__ void __launch_bounds__(256) attn_kernel() {
    int h = blockIdx.y, chunk = blockIdx.z;
    int lane = threadIdx.x & 31;
    int warp = threadIdx.x >> 5;
    int qbase = blockIdx.x * 128 + warp * 16;
    int g = lane >> 2, t4 = lane & 3;

    __shared__ uint32 Ksh[KT * 9];        // [key][8 bf16x2 dims + pad]
    __shared__ uint32 Vt[16 * 68];        // [dim][64 bf16x2 key-pairs + pad]

    const float SC = 0.25f * 1.44269504088896f;   // 1/sqrt(dh) * log2(e)
    // Q A-fragment (rows g, g+8; dim pairs 2t4, 2t4+8)
    uint32 qa[4];
    {
        const float* q0 = g_qkv + (qbase + g) * 192 + h * DH;
        const float* q1 = g_qkv + (qbase + g + 8) * 192 + h * DH;
        float2 v;
        v = *(const float2*)(q0 + 2 * t4);     qa[0] = packbf(v.x * SC, v.y * SC);
        v = *(const float2*)(q1 + 2 * t4);     qa[1] = packbf(v.x * SC, v.y * SC);
        v = *(const float2*)(q0 + 2 * t4 + 8); qa[2] = packbf(v.x * SC, v.y * SC);
        v = *(const float2*)(q1 + 2 * t4 + 8); qa[3] = packbf(v.x * SC, v.y * SC);
    }

    float o1[4] = {0.f, 0.f, 0.f, 0.f};
    float o2[4] = {0.f, 0.f, 0.f, 0.f};
    float lg = 0.f, lg8 = 0.f;
    const float zc[4] = {0.f, 0.f, 0.f, 0.f};

    for (int t = 0; t < CKEYS / KT; t++) {
        int key0 = chunk * CKEYS + t * KT;
        __syncthreads();
        // stage K (bf16x2 packed) and V (transposed [dim][key] bf16)
        for (int i = threadIdx.x; i < KT * 4; i += 256) {
            int j = i >> 2, c = i & 3;
            const float* base = g_qkv + (key0 + j) * 192 + 64 + h * DH + c * 4;
            float4 kv = *(const float4*)base;
            Ksh[j * 9 + c * 2]     = packbf(kv.x, kv.y);
            Ksh[j * 9 + c * 2 + 1] = packbf(kv.z, kv.w);
            float4 vv = *(const float4*)(base + 64);
            __nv_bfloat16* vt = (__nv_bfloat16*)Vt;
            vt[(c * 4 + 0) * 136 + j] = __float2bfloat16(vv.x);
            vt[(c * 4 + 1) * 136 + j] = __float2bfloat16(vv.y);
            vt[(c * 4 + 2) * 136 + j] = __float2bfloat16(vv.z);
            vt[(c * 4 + 3) * 136 + j] = __float2bfloat16(vv.w);
        }
        __syncthreads();

#pragma unroll
        for (int kk = 0; kk < KT; kk += 16) {
            // ---- S = Q K^T for 16 keys (2 mmas) ----
            uint32 kb10 = Ksh[(kk + g) * 9 + t4];
            uint32 kb11 = Ksh[(kk + g) * 9 + 4 + t4];
            uint32 kb20 = Ksh[(kk + 8 + g) * 9 + t4];
            uint32 kb21 = Ksh[(kk + 8 + g) * 9 + 4 + t4];
            float s1[4], s2[4];
            mma16816(s1, qa, kb10, kb11, zc);
            mma16816(s2, qa, kb20, kb21, zc);
            // ---- P = exp2(S), l accumulation ----
            s1[0] = ex2(s1[0]); s1[1] = ex2(s1[1]); s1[2] = ex2(s1[2]); s1[3] = ex2(s1[3]);
            s2[0] = ex2(s2[0]); s2[1] = ex2(s2[1]); s2[2] = ex2(s2[2]); s2[3] = ex2(s2[3]);
            lg  += (s1[0] + s1[1]) + (s2[0] + s2[1]);
            lg8 += (s1[2] + s1[3]) + (s2[2] + s2[3]);
            // ---- repack P as A-fragment (C->A identity) ----
            uint32 pa[4];
            pa[0] = packbf(s1[0], s1[1]);
            pa[1] = packbf(s1[2], s1[3]);
            pa[2] = packbf(s2[0], s2[1]);
            pa[3] = packbf(s2[2], s2[3]);
            // ---- O += P V (2 mmas: dims 0-7, 8-15) ----
            int k2 = kk >> 1;
            uint32 vb10 = Vt[g * 68 + k2 + t4];
            uint32 vb11 = Vt[g * 68 + k2 + 4 + t4];
            uint32 vb20 = Vt[(g + 8) * 68 + k2 + t4];
            uint32 vb21 = Vt[(g + 8) * 68 + k2 + 4 + t4];
            mma16816(o1, pa, vb10, vb11, o1);
            mma16816(o2, pa, vb20, vb21, o2);
        }
    }

    // quad-reduce l across the 4 threads sharing each row
    lg  += __shfl_xor_sync(0xFFFFFFFF, lg, 1);
    lg  += __shfl_xor_sync(0xFFFFFFFF, lg, 2);
    lg8 += __shfl_xor_sync(0xFFFFFFFF, lg8, 1);
    lg8 += __shfl_xor_sync(0xFFFFFFFF, lg8, 2);

    size_t base = ((size_t)(h * CHUNKS + chunk)) * NN;
    size_t idxA = base + qbase + g;
    size_t idxB = base + qbase + g + 8;
    // row g: dims (2t4, 2t4+1) from o1[0..1], dims (8+2t4, +1) from o2[0..1]
    *(float2*)&g_pacc[idxA * DH + 2 * t4]     = make_float2(o1[0], o1[1]);
    *(float2*)&g_pacc[idxA * DH + 8 + 2 * t4] = make_float2(o2[0], o2[1]);
    *(float2*)&g_pacc[idxB * DH + 2 * t4]     = make_float2(o1[2], o1[3]);
    *(float2*)&g_pacc[idxB * DH + 8 + 2 * t4] = make_float2(o2[2], o2[3]);
    if (t4 == 0) {
        g_pl[idxA] = lg;
        g_pl[idxB] = lg8;
    }
}

// ------------------------- GCN2 scatter: warp/edge, 22 v4 lanes ------------
__global__ void scatter88_kernel(const int* __restrict__ ei, const float* __restrict__ ea) {
    int gtid = blockIdx.x * blockDim.x + threadIdx.x;
    int e = gtid >> 5;
    if (e >= EE) return;
    int lane = gtid & 31;
    if (lane >= 22) return;
    int s = ei[e];
    int d = ei[EE + e];
    float coef = rsqrtf(g_deg[s]) * ea[e] * rsqrtf(g_deg[d]);
    float4 v = *(const float4*)&g_h2w[s * OUTP + lane * 4];
    float* p = &g_agg2[d * OUTP + lane * 4];
    asm volatile("red.global.add.v4.f32 [%0], {%1,%2,%3,%4};"
                 :: "l"(p), "f"(coef * v.x), "f"(coef * v.y),
                    "f"(coef * v.z), "f"(coef * v.w) : "memory");
}

__global__ void final_node_kernel(const int* __restrict__ batch, const float* __restrict__ b2) {
    int idx = blockIdx.x * blockDim.x + threadIdx.x;
    if (idx >= NN * OUTP) return;
    int i = idx / OUTP, f = idx - i * OUTP;
    if (f >= OUTD) return;
    float d2 = __frcp_rn(g_deg[i]);
    float v = g_agg2[idx] + d2 * g_h2w[idx] + b2[f];
    atomicAdd(&g_pool[batch[i] * OUTD + f], v);
}

__global__ void out_kernel(float* __restrict__ out) {
    int idx = blockIdx.x * blockDim.x + threadIdx.x;
    if (idx >= BB * OUTD) return;
    int b = idx / OUTD;
    out[idx] = g_pool[idx] / fmaxf(g_cnt[b], 1.0f);
}

// ------------------------- launch ------------------------------------------
extern "C" void kernel_launch(void* const* d_in, const int* in_sizes, int n_in,
                              void* d_out, int out_size) {
    const float* x     = (const float*)d_in[0];
    const int*   ei    = (const int*)  d_in[1];
    const float* ea    = (const float*)d_in[2];
    const int*   batch = (const int*)  d_in[3];
    const float* W1    = (const float*)d_in[4];
    const float* b1    = (const float*)d_in[5];
    const float* Win   = (const float*)d_in[6];
    const float* b_in  = (const float*)d_in[7];
    const float* Wout  = (const float*)d_in[8];
    const float* b_out = (const float*)d_in[9];
    const float* W2    = (const float*)d_in[10];
    const float* b2    = (const float*)d_in[11];
    float* out = (float*)d_out;

    float *p_hw, *p_qkv, *p_h2w, *p_Wc, *p_bc;
    cudaGetSymbolAddress((void**)&p_hw,  g_hw);
    cudaGetSymbolAddress((void**)&p_qkv, g_qkv);
    cudaGetSymbolAddress((void**)&p_h2w, g_h2w);
    cudaGetSymbolAddress((void**)&p_Wc,  g_Wc);
    cudaGetSymbolAddress((void**)&p_bc,  g_bc);

    // 0. prep: zero accumulators + fold Wout into W2
    prep_kernel<<<(NN * OUTP + 255) / 256, 256>>>(W2, Wout, b_out);
    // 1. GCN1 linear (independent of graph prep)
    rowgemm<64, 64, false, 0><<<NN / 16, 256>>>(x, W1, nullptr, nullptr, p_hw);
    // 2. degree + batch counts
    accum_kernel<<<EE / 256, 256>>>(ei, ea, batch);
    // 3. GCN1 aggregate (inline rsqrt norm)
    scatter64_kernel<<<EE * 16 / 256, 256>>>(ei, ea);
    // 4. QKV projection with fused GCN1 post
    rowgemm<192, 192, true, 1><<<NN / 16, 256>>>(nullptr, Win, b_in, b1, p_qkv);
    // 5. attention (tensor-core split-K partials)
    attn_kernel<<<dim3(NN / 128, NHEADS, CHUNKS), 256>>>();
    // 6. fused (Wout∘W2) linear with fused attention combine
    rowgemm<86, 88, true, 2><<<NN / 16, 256>>>(nullptr, p_Wc, p_bc, nullptr, p_h2w);
    // 7. GCN2 aggregate + pool
    scatter88_kernel<<<EE * 32 / 256, 256>>>(ei, ea);
    final_node_kernel<<<(NN * OUTP + 255) / 256, 256>>>(batch, b2);
    out_kernel<<<(BB * OUTD + 255) / 256, 256>>>(out);
}